// round 14
// baseline (speedup 1.0000x reference)
#include <cuda_runtime.h>
#include <cuda_fp16.h>
#include <math.h>
#include <stdint.h>

// EnhancedSparseAttention: B=1, C=256, H=W=64 (N=4096), 8 heads, hd=32
//  0) cvt: x, Wq/Wk/Wv/Wo -> fp16
//  1) merged launch: q/k/v GEMM (fp16 tensor core)  +  mask bit-packing
//  2) flash attention (fp16 mma); mask from packed bits (2 LDG.64/thread/iter)
//  3) y2 = x + Wo @ att + bo  fp16 tensor-core GEMM, fp32 accum/output
//  4) LayerNorm over channels, write [c][n]
// mask arrives as int32 (bool -> int32 harness conversion).

constexpr int CH   = 256;
constexpr int NPIX = 4096;
constexpr int NH   = 8;
constexpr int HD   = 32;

__device__ __half g_qh  [NPIX * CH];
__device__ __half g_kh  [NPIX * CH];
__device__ __half g_vh  [NPIX * CH];
__device__ __half g_xh  [CH * NPIX];
__device__ __half g_wqh [CH * CH];
__device__ __half g_wkh [CH * CH];
__device__ __half g_wvh [CH * CH];
__device__ __half g_woh [CH * CH];
__device__ __half g_atth[NPIX * CH];
__device__ float  g_y2  [NPIX * CH];
__device__ unsigned long long g_mpk[(size_t)NH * NPIX * 64];   // packed mask bits

// ---------------------------------------------------------------------------
// fp32 exp2 (x <= 0), used only for the per-block alpha rescales.
__device__ __forceinline__ float fexp2(float x) {
    x = fmaxf(x, -126.0f);
    float r = x + 12582912.0f;            // 1.5*2^23: RN -> integer in low bits
    int   i = __float_as_int(r);
    float f = x - (r - 12582912.0f);      // f in [-0.5, 0.5]
    float p = fmaf(f, 1.3333558e-3f, 9.6181291e-3f);
    p = fmaf(f, p, 5.5504109e-2f);
    p = fmaf(f, p, 2.4022651e-1f);
    p = fmaf(f, p, 6.9314718e-1f);
    p = fmaf(f, p, 1.0f);
    return p * __int_as_float((i + (int)(127 - 0x4B400000)) << 23);
}

// half2 exp2 for x <= 0 (scores - rowmax). Clamp at -14; inputs <= -13.75
// (incl. masked -inf) produce exactly 0.
__device__ __forceinline__ __half2 h2exp2_nz(__half2 x) {
    __half2 xc = __hmax2(x, __float2half2_rn(-14.0f));
    __half2 mg = __float2half2_rn(1536.0f);           // 1.5*2^10
    __half2 r  = __hadd2(xc, mg);                     // RN -> int in mantissa
    __half2 f  = __hsub2(xc, __hsub2(r, mg));         // f in [-0.5, 0.5]
    __half2 p  = __hfma2(f, __float2half2_rn(9.6181291e-3f), __float2half2_rn(5.5504109e-2f));
    p = __hfma2(f, p, __float2half2_rn(2.4022651e-1f));
    p = __hfma2(f, p, __float2half2_rn(6.9314718e-1f));
    p = __hfma2(f, p, __float2half2_rn(1.0f));
    unsigned ru = *reinterpret_cast<unsigned*>(&r);
    unsigned eu = ((ru & 0x03FF03FFu) - 0x01F101F1u) << 10;   // 2^n per lane
    __half2 e  = *reinterpret_cast<__half2*>(&eu);
    p = __hmul2(p, e);
    __half2 z = __hge2(x, __float2half2_rn(-13.75f)); // 1.0 keep / 0.0 kill
    return __hmul2(p, z);
}

// pack two f32 -> f16x2 (lo in low half)
__device__ __forceinline__ __half2 pkh2(float lo, float hi) {
    unsigned r;
    asm("cvt.rn.f16x2.f32 %0, %1, %2;" : "=r"(r) : "f"(hi), "f"(lo));
    return *reinterpret_cast<__half2*>(&r);
}
__device__ __forceinline__ unsigned h2u(__half2 h) {
    return *reinterpret_cast<unsigned*>(&h);
}

__device__ __forceinline__ void mma16h(float& c0, float& c1, float& c2, float& c3,
                                       unsigned a0, unsigned a1, unsigned a2, unsigned a3,
                                       unsigned b0, unsigned b1) {
    asm("mma.sync.aligned.m16n8k16.row.col.f32.f16.f16.f32 "
        "{%0,%1,%2,%3}, {%4,%5,%6,%7}, {%8,%9}, {%0,%1,%2,%3};"
        : "+f"(c0), "+f"(c1), "+f"(c2), "+f"(c3)
        : "r"(a0), "r"(a1), "r"(a2), "r"(a3), "r"(b0), "r"(b1));
}

__device__ __forceinline__ void ldsm4(unsigned& r0, unsigned& r1, unsigned& r2, unsigned& r3,
                                      const void* p) {
    unsigned a = (unsigned)__cvta_generic_to_shared(p);
    asm volatile("ldmatrix.sync.aligned.m8n8.x4.shared.b16 {%0,%1,%2,%3}, [%4];"
                 : "=r"(r0), "=r"(r1), "=r"(r2), "=r"(r3) : "r"(a));
}
__device__ __forceinline__ void ldsm4t(unsigned& r0, unsigned& r1, unsigned& r2, unsigned& r3,
                                       const void* p) {
    unsigned a = (unsigned)__cvta_generic_to_shared(p);
    asm volatile("ldmatrix.sync.aligned.m8n8.x4.trans.shared.b16 {%0,%1,%2,%3}, [%4];"
                 : "=r"(r0), "=r"(r1), "=r"(r2), "=r"(r3) : "r"(a));
}
__device__ __forceinline__ void cpa16(void* dst, const void* src) {
    unsigned d = (unsigned)__cvta_generic_to_shared(dst);
    asm volatile("cp.async.ca.shared.global [%0], [%1], 16;" :: "r"(d), "l"(src));
}

// ---------------------------------------------------------------------------
// fp32 -> fp16: x (262144 vec4) + Wq/Wk/Wv/Wo (16384 vec4 each) = 327680
__global__ __launch_bounds__(256) void cvt_kernel(
    const float* __restrict__ x,
    const float* __restrict__ Wq, const float* __restrict__ Wk,
    const float* __restrict__ Wv, const float* __restrict__ Wo)
{
    int idx = blockIdx.x * 256 + threadIdx.x;
    const float4* src;
    uint2* dst;
    int base;
    if (idx < 262144)      { src = (const float4*)x;  dst = (uint2*)g_xh;  base = idx; }
    else if (idx < 278528) { src = (const float4*)Wq; dst = (uint2*)g_wqh; base = idx - 262144; }
    else if (idx < 294912) { src = (const float4*)Wk; dst = (uint2*)g_wkh; base = idx - 278528; }
    else if (idx < 311296) { src = (const float4*)Wv; dst = (uint2*)g_wvh; base = idx - 294912; }
    else                   { src = (const float4*)Wo; dst = (uint2*)g_woh; base = idx - 311296; }
    float4 v = src[base];
    uint2 o = { h2u(pkh2(v.x, v.y)), h2u(pkh2(v.z, v.w)) };
    dst[base] = o;
}

// ---------------------------------------------------------------------------
// Merged kernel: blocks 0-383 do the fp16 QKV GEMM; blocks 384-4479 bit-pack
// the mask (one warp per row; 64 int32 -> one uint64 via two ballots).
__global__ __launch_bounds__(256) void qkv_pack_kernel(
    const float* __restrict__ bq, const float* __restrict__ bk,
    const float* __restrict__ bv, const int* __restrict__ mask)
{
    __shared__ alignas(16) __half Xs[2][32][136];
    __shared__ alignas(16) __half Ws[2][64][40];

    if (blockIdx.x >= 384) {
        // ---- mask packing ----
        int wid  = (blockIdx.x - 384) * 8 + (threadIdx.x >> 5);  // row 0..32767
        int lane = threadIdx.x & 31;
        const int* row = mask + (size_t)wid * NPIX;
        unsigned long long* dst = g_mpk + (size_t)wid * 64;
        for (int kb = 0; kb < 64; kb += 4) {
            unsigned long long v0, v1, v2, v3;
            {
                int a0 = __ldg(&row[(kb + 0) * 64 + lane]);
                int a1 = __ldg(&row[(kb + 0) * 64 + 32 + lane]);
                int b0 = __ldg(&row[(kb + 1) * 64 + lane]);
                int b1 = __ldg(&row[(kb + 1) * 64 + 32 + lane]);
                int c0 = __ldg(&row[(kb + 2) * 64 + lane]);
                int c1 = __ldg(&row[(kb + 2) * 64 + 32 + lane]);
                int d0 = __ldg(&row[(kb + 3) * 64 + lane]);
                int d1 = __ldg(&row[(kb + 3) * 64 + 32 + lane]);
                v0 = ((unsigned long long)__ballot_sync(0xffffffffu, a1 != 0) << 32)
                   | __ballot_sync(0xffffffffu, a0 != 0);
                v1 = ((unsigned long long)__ballot_sync(0xffffffffu, b1 != 0) << 32)
                   | __ballot_sync(0xffffffffu, b0 != 0);
                v2 = ((unsigned long long)__ballot_sync(0xffffffffu, c1 != 0) << 32)
                   | __ballot_sync(0xffffffffu, c0 != 0);
                v3 = ((unsigned long long)__ballot_sync(0xffffffffu, d1 != 0) << 32)
                   | __ballot_sync(0xffffffffu, d0 != 0);
            }
            unsigned long long out = (lane == 0) ? v0 : (lane == 1) ? v1
                                   : (lane == 2) ? v2 : v3;
            if (lane < 4) dst[kb + lane] = out;   // 32B coalesced per warp
        }
        return;
    }

    // ---- QKV GEMM (identical to validated gemm_qkv_h; bx decode) ----
    int yy  = blockIdx.x >> 5;              // 0..11
    int sel = yy >> 2;
    const __half* Wsrc = (sel == 0) ? g_wqh : (sel == 1) ? g_wkh : g_wvh;
    const float* bias  = (sel == 0) ? bq : (sel == 1) ? bk : bv;
    __half* Y          = (sel == 0) ? g_qh : (sel == 1) ? g_kh : g_vh;
    const float os = (sel == 0) ? (0.17677669529663687f * 1.4426950408889634f) : 1.0f;

    int t = threadIdx.x, lane = t & 31, w = t >> 5;
    int nb = (blockIdx.x & 31) * 128, ob = (yy & 3) * 64;
    int gr = lane >> 2, qt = lane & 3;
    int g  = lane >> 3;

    int xrow = t >> 3, xcol = (t & 7) * 16;
    int wrow = t >> 2, wcol = (t & 3) * 8;
    const __half* xsrc = g_xh + (size_t)xrow * NPIX + nb + xcol;
    const __half* wsrc = Wsrc + (size_t)(ob + wrow) * CH + wcol;

    float acc[8][4] = {};

    cpa16(&Xs[0][xrow][xcol],     xsrc);
    cpa16(&Xs[0][xrow][xcol + 8], xsrc + 8);
    cpa16(&Ws[0][wrow][wcol],     wsrc);
    asm volatile("cp.async.commit_group;");

    for (int c = 0; c < 8; c++) {
        int b = c & 1;
        if (c < 7) {
            const __half* xs = xsrc + (size_t)(c + 1) * 32 * NPIX;
            const __half* ws = wsrc + (c + 1) * 32;
            cpa16(&Xs[b ^ 1][xrow][xcol],     xs);
            cpa16(&Xs[b ^ 1][xrow][xcol + 8], xs + 8);
            cpa16(&Ws[b ^ 1][wrow][wcol],     ws);
            asm volatile("cp.async.commit_group;");
            asm volatile("cp.async.wait_group 1;");
        } else {
            asm volatile("cp.async.wait_group 0;");
        }
        __syncthreads();

        unsigned aa0[4], aa1[4];
        ldsm4t(aa0[0], aa0[2], aa0[1], aa0[3],
               &Xs[b][(g & 1) * 8 + (lane & 7)][16 * w + (g >> 1) * 8]);
        ldsm4t(aa1[0], aa1[2], aa1[1], aa1[3],
               &Xs[b][16 + (g & 1) * 8 + (lane & 7)][16 * w + (g >> 1) * 8]);

        #pragma unroll
        for (int nt = 0; nt < 8; nt++) {
            unsigned b0, b1, b2, b3;
            ldsm4(b0, b1, b2, b3, &Ws[b][nt * 8 + (lane & 7)][(lane >> 3) * 8]);
            mma16h(acc[nt][0], acc[nt][1], acc[nt][2], acc[nt][3],
                   aa0[0], aa0[1], aa0[2], aa0[3], b0, b1);
            mma16h(acc[nt][0], acc[nt][1], acc[nt][2], acc[nt][3],
                   aa1[0], aa1[1], aa1[2], aa1[3], b2, b3);
        }
        __syncthreads();
    }

    int r0 = nb + 16 * w + gr, r1 = r0 + 8;
    #pragma unroll
    for (int nt = 0; nt < 8; nt++) {
        int col = ob + nt * 8 + 2 * qt;
        float2 bv2 = *(const float2*)&bias[col];
        unsigned lo = h2u(pkh2(os * (acc[nt][0] + bv2.x), os * (acc[nt][1] + bv2.y)));
        unsigned hi = h2u(pkh2(os * (acc[nt][2] + bv2.x), os * (acc[nt][3] + bv2.y)));
        *(unsigned*)&Y[(size_t)r0 * CH + col] = lo;
        *(unsigned*)&Y[(size_t)r1 * CH + col] = hi;
    }
}

// ---------------------------------------------------------------------------
// fp16 tensor-core output GEMM with residual (R10 shape: 64-col tiles).
__global__ __launch_bounds__(256) void gemm_o_h(
    const float* __restrict__ bias, const float* __restrict__ resid)
{
    __shared__ alignas(16) __half As[2][128][40];
    __shared__ alignas(16) __half Ws[2][64][40];

    int t = threadIdx.x, lane = t & 31, w = t >> 5;
    int nb = blockIdx.x * 128, ob = blockIdx.y * 64;
    int gr = lane >> 2, qt = lane & 3;

    int arow = t >> 1, acol = (t & 1) * 16;
    int wrow = t >> 2, wcol = (t & 3) * 8;
    const __half* asrc = g_atth + (size_t)(nb + arow) * CH + acol;
    const __half* wsrc = g_woh + (size_t)(ob + wrow) * CH + wcol;

    float acc[8][4] = {};

    cpa16(&As[0][arow][acol],     asrc);
    cpa16(&As[0][arow][acol + 8], asrc + 8);
    cpa16(&Ws[0][wrow][wcol],     wsrc);
    asm volatile("cp.async.commit_group;");

    for (int c = 0; c < 8; c++) {
        int b = c & 1;
        if (c < 7) {
            const __half* as = asrc + (c + 1) * 32;
            const __half* ws = wsrc + (c + 1) * 32;
            cpa16(&As[b ^ 1][arow][acol],     as);
            cpa16(&As[b ^ 1][arow][acol + 8], as + 8);
            cpa16(&Ws[b ^ 1][wrow][wcol],     ws);
            asm volatile("cp.async.commit_group;");
            asm volatile("cp.async.wait_group 1;");
        } else {
            asm volatile("cp.async.wait_group 0;");
        }
        __syncthreads();

        unsigned aa0[4], aa1[4];
        ldsm4(aa0[0], aa0[1], aa0[2], aa0[3],
              &As[b][16 * w + (lane & 15)][(lane >> 4) * 8]);
        ldsm4(aa1[0], aa1[1], aa1[2], aa1[3],
              &As[b][16 * w + (lane & 15)][16 + (lane >> 4) * 8]);

        #pragma unroll
        for (int nt = 0; nt < 8; nt++) {
            unsigned b0, b1, b2, b3;
            ldsm4(b0, b1, b2, b3, &Ws[b][nt * 8 + (lane & 7)][(lane >> 3) * 8]);
            mma16h(acc[nt][0], acc[nt][1], acc[nt][2], acc[nt][3],
                   aa0[0], aa0[1], aa0[2], aa0[3], b0, b1);
            mma16h(acc[nt][0], acc[nt][1], acc[nt][2], acc[nt][3],
                   aa1[0], aa1[1], aa1[2], aa1[3], b2, b3);
        }
        __syncthreads();
    }

    int r0 = nb + 16 * w + gr, r1 = r0 + 8;
    #pragma unroll
    for (int nt = 0; nt < 8; nt++) {
        int col = ob + nt * 8 + 2 * qt;
        float2 bv2 = *(const float2*)&bias[col];
        float2 lo = { acc[nt][0] + bv2.x + resid[(size_t)col * NPIX + r0],
                      acc[nt][1] + bv2.y + resid[(size_t)(col + 1) * NPIX + r0] };
        float2 hi = { acc[nt][2] + bv2.x + resid[(size_t)col * NPIX + r1],
                      acc[nt][3] + bv2.y + resid[(size_t)(col + 1) * NPIX + r1] };
        *(float2*)&g_y2[(size_t)r0 * CH + col] = lo;
        *(float2*)&g_y2[(size_t)r1 * CH + col] = hi;
    }
}

// ---------------------------------------------------------------------------
// Flash attention (R10 structure). CTA: 1 head x 128 q-rows, 8 warps.
// Mask from packed bits: 2x LDG.64 per thread per key-block.
__global__ __launch_bounds__(256, 2) void attn_kernel()
{
    __shared__ alignas(16) __half Ksh[2][64][40];
    __shared__ alignas(16) __half Vsh[2][64][40];

    const unsigned F = 0xffffffffu;
    int t    = threadIdx.x;
    int lane = t & 31;
    int w    = t >> 5;
    int h    = blockIdx.y;
    int qb   = blockIdx.x * 128;
    int gr   = lane >> 2;
    int qt   = lane & 3;
    int hoff = h * HD;

    int r_lo = qb + w * 16 + gr;
    int r_hi = r_lo + 8;

    unsigned qa[2][4];
    {
        const __half* ql  = g_qh + (size_t)r_lo * CH + hoff;
        const __half* qh2 = g_qh + (size_t)r_hi * CH + hoff;
        #pragma unroll
        for (int kc = 0; kc < 2; kc++) {
            qa[kc][0] = *(const unsigned*)(ql  + 16 * kc + 2 * qt);
            qa[kc][1] = *(const unsigned*)(qh2 + 16 * kc + 2 * qt);
            qa[kc][2] = *(const unsigned*)(ql  + 16 * kc + 8 + 2 * qt);
            qa[kc][3] = *(const unsigned*)(qh2 + 16 * kc + 8 + 2 * qt);
        }
    }

    int su   = t & 127;
    int skey = su >> 1, shh = su & 1;
    const __half* src0 = ((t >= 128) ? g_vh : g_kh) + (size_t)skey * CH + hoff + shh * 16;
    __half* dst0 = (t >= 128) ? &Vsh[0][skey][shh * 16] : &Ksh[0][skey][shh * 16];
    __half* dst1 = (t >= 128) ? &Vsh[1][skey][shh * 16] : &Ksh[1][skey][shh * 16];

    float oc[4][4] = {};
    float Lc0 = 0.f, Lc1 = 0.f, Lc2 = 0.f, Lc3 = 0.f;
    float M0 = -1e30f, M1 = -1e30f;

    const unsigned bL = (gr == 0) ? 0x3C003C00u : 0u;

    const unsigned long long* mp_lo = g_mpk + (size_t)(h * NPIX + r_lo) * 64;
    const unsigned long long* mp_hi = g_mpk + (size_t)(h * NPIX + r_hi) * 64;
    int sh0 = 2 * qt;                      // base bit shift for this thread

    cpa16(dst0,     src0);
    cpa16(dst0 + 8, src0 + 8);
    asm volatile("cp.async.commit_group;");

    for (int kb = 0; kb < 64; kb++) {
        int b = kb & 1;
        if (kb < 63) {
            const __half* s = src0 + (size_t)(kb + 1) * 64 * CH;
            __half* d = b ? dst0 : dst1;
            cpa16(d,     s);
            cpa16(d + 8, s + 8);
            asm volatile("cp.async.commit_group;");
        }

        // packed mask bits for this 64-key block (issued before the wait)
        unsigned long long blo = __ldg(&mp_lo[kb]);
        unsigned long long bhi = __ldg(&mp_hi[kb]);

        if (kb < 63) asm volatile("cp.async.wait_group 1;");
        else         asm volatile("cp.async.wait_group 0;");
        __syncthreads();

        float sc[8][4];
        #pragma unroll
        for (int nt = 0; nt < 8; nt++) {
            unsigned r0, r1, r2, r3;
            ldsm4(r0, r1, r2, r3, &Ksh[b][nt * 8 + (lane & 7)][(lane >> 3) * 8]);
            float c0 = 0.f, c1 = 0.f, c2 = 0.f, c3 = 0.f;
            mma16h(c0, c1, c2, c3, qa[0][0], qa[0][1], qa[0][2], qa[0][3], r0, r1);
            mma16h(c0, c1, c2, c3, qa[1][0], qa[1][1], qa[1][2], qa[1][3], r2, r3);
            unsigned ml = (unsigned)(blo >> (nt * 8 + sh0));
            unsigned mh = (unsigned)(bhi >> (nt * 8 + sh0));
            sc[nt][0] = (ml & 1u) ? c0 : -1e30f;
            sc[nt][1] = (ml & 2u) ? c1 : -1e30f;
            sc[nt][2] = (mh & 1u) ? c2 : -1e30f;
            sc[nt][3] = (mh & 2u) ? c3 : -1e30f;
        }

        float m_lo = -1e30f, m_hi = -1e30f;
        #pragma unroll
        for (int nt = 0; nt < 8; nt++) {
            m_lo = fmaxf(m_lo, fmaxf(sc[nt][0], sc[nt][1]));
            m_hi = fmaxf(m_hi, fmaxf(sc[nt][2], sc[nt][3]));
        }
        m_lo = fmaxf(m_lo, __shfl_xor_sync(F, m_lo, 1));
        m_lo = fmaxf(m_lo, __shfl_xor_sync(F, m_lo, 2));
        m_hi = fmaxf(m_hi, __shfl_xor_sync(F, m_hi, 1));
        m_hi = fmaxf(m_hi, __shfl_xor_sync(F, m_hi, 2));

        float Mn0 = fmaxf(M0, m_lo), Mn1 = fmaxf(M1, m_hi);
        float a0 = fexp2(M0 - Mn0), a1 = fexp2(M1 - Mn1);
        M0 = Mn0; M1 = Mn1;

        __half2 mh0 = __float2half2_rn(Mn0);
        __half2 mh1 = __float2half2_rn(Mn1);

        #pragma unroll
        for (int dt = 0; dt < 4; dt++) {
            oc[dt][0] *= a0; oc[dt][1] *= a0;
            oc[dt][2] *= a1; oc[dt][3] *= a1;
        }
        Lc0 *= a0; Lc2 *= a1;

        int vrow0 = ((lane >> 3) & 1) * 8 + (lane & 7);
        int vcol0 = ((lane >> 3) >> 1) * 8;
        #pragma unroll
        for (int j = 0; j < 4; j++) {
            __half2 pa0 = h2exp2_nz(__hsub2(pkh2(sc[2*j][0],   sc[2*j][1]),   mh0));
            __half2 pa1 = h2exp2_nz(__hsub2(pkh2(sc[2*j][2],   sc[2*j][3]),   mh1));
            __half2 pa2 = h2exp2_nz(__hsub2(pkh2(sc[2*j+1][0], sc[2*j+1][1]), mh0));
            __half2 pa3 = h2exp2_nz(__hsub2(pkh2(sc[2*j+1][2], sc[2*j+1][3]), mh1));
            unsigned a0u = h2u(pa0), a1u = h2u(pa1), a2u = h2u(pa2), a3u = h2u(pa3);
            unsigned b0, b1, b2, b3;
            ldsm4t(b0, b1, b2, b3, &Vsh[b][16 * j + vrow0][vcol0]);
            mma16h(oc[0][0], oc[0][1], oc[0][2], oc[0][3], a0u, a1u, a2u, a3u, b0, b1);
            mma16h(oc[1][0], oc[1][1], oc[1][2], oc[1][3], a0u, a1u, a2u, a3u, b2, b3);
            ldsm4t(b0, b1, b2, b3, &Vsh[b][16 * j + vrow0][16 + vcol0]);
            mma16h(oc[2][0], oc[2][1], oc[2][2], oc[2][3], a0u, a1u, a2u, a3u, b0, b1);
            mma16h(oc[3][0], oc[3][1], oc[3][2], oc[3][3], a0u, a1u, a2u, a3u, b2, b3);
            mma16h(Lc0, Lc1, Lc2, Lc3, a0u, a1u, a2u, a3u, bL, bL);
        }

        __syncthreads();
    }

    float L_lo = __shfl_sync(F, Lc0, lane & ~3);
    float L_hi = __shfl_sync(F, Lc2, lane & ~3);

    float rl0 = 1.0f / L_lo;
    float rl1 = 1.0f / L_hi;
    #pragma unroll
    for (int dt = 0; dt < 4; dt++) {
        int cb = hoff + dt * 8 + 2 * qt;
        unsigned lo = h2u(pkh2(oc[dt][0] * rl0, oc[dt][1] * rl0));
        unsigned hi = h2u(pkh2(oc[dt][2] * rl1, oc[dt][3] * rl1));
        *(unsigned*)&g_atth[(size_t)r_lo * CH + cb] = lo;
        *(unsigned*)&g_atth[(size_t)r_hi * CH + cb] = hi;
    }
}

// ---------------------------------------------------------------------------
__global__ __launch_bounds__(256) void ln_kernel(
    const float* __restrict__ gamma, const float* __restrict__ beta,
    float* __restrict__ out)
{
    __shared__ float tile[32][257];
    __shared__ float mu_s[32], rs_s[32];
    const unsigned FULL = 0xffffffffu;

    int t    = threadIdx.x;
    int pb   = blockIdx.x * 32;
    int lane = t & 31;
    int w    = t >> 5;

    #pragma unroll
    for (int i = 0; i < 32; i++)
        tile[i][t] = g_y2[(size_t)(pb + i) * CH + t];
    __syncthreads();

    #pragma unroll
    for (int pi = 0; pi < 4; pi++) {
        int p = w + 8 * pi;
        float sm = 0.f, sq = 0.f;
        #pragma unroll
        for (int c = 0; c < CH; c += 32) {
            float xv = tile[p][c + lane];
            sm += xv;
            sq  = fmaf(xv, xv, sq);
        }
        #pragma unroll
        for (int off = 16; off > 0; off >>= 1) {
            sm += __shfl_xor_sync(FULL, sm, off);
            sq += __shfl_xor_sync(FULL, sq, off);
        }
        if (lane == 0) {
            float mu  = sm * (1.0f / CH);
            float var = sq * (1.0f / CH) - mu * mu;
            mu_s[p] = mu;
            rs_s[p] = rsqrtf(var + 1e-5f);
        }
    }
    __syncthreads();

    float mu = mu_s[lane];
    float rs = rs_s[lane];
    #pragma unroll
    for (int i = 0; i < 32; i++) {
        int c = w + 8 * i;
        float g = gamma[c], b = beta[c];
        out[(size_t)c * NPIX + pb + lane] = (tile[lane][c] - mu) * rs * g + b;
    }
}

// ---------------------------------------------------------------------------
extern "C" void kernel_launch(void* const* d_in, const int* in_sizes, int n_in,
                              void* d_out, int out_size)
{
    const float* x    = (const float*)d_in[0];
    const int*   mask = (const int*)d_in[1];
    const float* Wq = (const float*)d_in[2];
    const float* bq = (const float*)d_in[3];
    const float* Wk = (const float*)d_in[4];
    const float* bk = (const float*)d_in[5];
    const float* Wv = (const float*)d_in[6];
    const float* bv = (const float*)d_in[7];
    const float* Wo = (const float*)d_in[8];
    const float* bo = (const float*)d_in[9];
    const float* gamma = (const float*)d_in[10];
    const float* beta  = (const float*)d_in[11];
    float* out = (float*)d_out;

    cvt_kernel<<<1280, 256>>>(x, Wq, Wk, Wv, Wo);
    qkv_pack_kernel<<<4480, 256>>>(bq, bk, bv, mask);
    attn_kernel<<<dim3(NPIX / 128, NH), 256>>>();
    gemm_o_h<<<dim3(NPIX / 128, CH / 64), 256>>>(bo, x);
    ln_kernel<<<NPIX / 32, 256>>>(gamma, beta, out);
}

// round 15
// speedup vs baseline: 1.5586x; 1.5586x over previous
#include <cuda_runtime.h>
#include <cuda_fp16.h>
#include <math.h>
#include <stdint.h>

// EnhancedSparseAttention: B=1, C=256, H=W=64 (N=4096), 8 heads, hd=32
//  0) cvt: x, Wq/Wk/Wv/Wo -> fp16
//  1) q/k/v = W @ x + b       fp16 tensor-core GEMM -> fp16 [n][c] (q scaled)
//  2) flash attention (fp16 mma); half2 softmax; mask applied AFTER exp via
//     zero-multiply (softmax ratio is offset-invariant); 3-stage cp.async,
//     single barrier per iteration
//  3) y2 = x + Wo @ att + bo  fp16 tensor-core GEMM, fp32 accum/output
//  4) LayerNorm over channels, write [c][n]
// mask arrives as int32 0/1 (bool -> int32 harness conversion).

constexpr int CH   = 256;
constexpr int NPIX = 4096;
constexpr int NH   = 8;
constexpr int HD   = 32;

__device__ __half g_qh  [NPIX * CH];
__device__ __half g_kh  [NPIX * CH];
__device__ __half g_vh  [NPIX * CH];
__device__ __half g_xh  [CH * NPIX];
__device__ __half g_wqh [CH * CH];
__device__ __half g_wkh [CH * CH];
__device__ __half g_wvh [CH * CH];
__device__ __half g_woh [CH * CH];
__device__ __half g_atth[NPIX * CH];
__device__ float  g_y2  [NPIX * CH];

// ---------------------------------------------------------------------------
// fp32 exp2 (x <= 0), used only for the per-block alpha rescales.
__device__ __forceinline__ float fexp2(float x) {
    x = fmaxf(x, -126.0f);
    float r = x + 12582912.0f;            // 1.5*2^23: RN -> integer in low bits
    int   i = __float_as_int(r);
    float f = x - (r - 12582912.0f);      // f in [-0.5, 0.5]
    float p = fmaf(f, 1.3333558e-3f, 9.6181291e-3f);
    p = fmaf(f, p, 5.5504109e-2f);
    p = fmaf(f, p, 2.4022651e-1f);
    p = fmaf(f, p, 6.9314718e-1f);
    p = fmaf(f, p, 1.0f);
    return p * __int_as_float((i + (int)(127 - 0x4B400000)) << 23);
}

// half2 exp2 for x <= 0 with external zero-mask z (half2 {1,0} bit pattern).
// Clamp at -14 (genuine scores never reach it; masked entries killed by z).
__device__ __forceinline__ __half2 h2exp2z(__half2 x, unsigned zu) {
    __half2 xc = __hmax2(x, __float2half2_rn(-14.0f));
    __half2 mg = __float2half2_rn(1536.0f);           // 1.5*2^10
    __half2 r  = __hadd2(xc, mg);                     // RN -> int in mantissa
    __half2 f  = __hsub2(xc, __hsub2(r, mg));         // f in [-0.5, 0.5]
    __half2 p  = __hfma2(f, __float2half2_rn(9.6181291e-3f), __float2half2_rn(5.5504109e-2f));
    p = __hfma2(f, p, __float2half2_rn(2.4022651e-1f));
    p = __hfma2(f, p, __float2half2_rn(6.9314718e-1f));
    p = __hfma2(f, p, __float2half2_rn(1.0f));
    unsigned ru = *reinterpret_cast<unsigned*>(&r);
    unsigned eu = ((ru & 0x03FF03FFu) - 0x01F101F1u) << 10;   // 2^n per lane
    __half2 e = *reinterpret_cast<__half2*>(&eu);
    __half2 z = *reinterpret_cast<__half2*>(&zu);
    return __hmul2(__hmul2(p, e), z);
}

// pack two f32 -> f16x2 (lo in low half)
__device__ __forceinline__ __half2 pkh2(float lo, float hi) {
    unsigned r;
    asm("cvt.rn.f16x2.f32 %0, %1, %2;" : "=r"(r) : "f"(hi), "f"(lo));
    return *reinterpret_cast<__half2*>(&r);
}
__device__ __forceinline__ unsigned h2u(__half2 h) {
    return *reinterpret_cast<unsigned*>(&h);
}
__device__ __forceinline__ __half2 hmax2shfl(__half2 v, int m) {
    unsigned o = __shfl_xor_sync(0xffffffffu, h2u(v), m);
    return __hmax2(v, *reinterpret_cast<__half2*>(&o));
}

__device__ __forceinline__ void mma16h(float& c0, float& c1, float& c2, float& c3,
                                       unsigned a0, unsigned a1, unsigned a2, unsigned a3,
                                       unsigned b0, unsigned b1) {
    asm("mma.sync.aligned.m16n8k16.row.col.f32.f16.f16.f32 "
        "{%0,%1,%2,%3}, {%4,%5,%6,%7}, {%8,%9}, {%0,%1,%2,%3};"
        : "+f"(c0), "+f"(c1), "+f"(c2), "+f"(c3)
        : "r"(a0), "r"(a1), "r"(a2), "r"(a3), "r"(b0), "r"(b1));
}

__device__ __forceinline__ void ldsm4(unsigned& r0, unsigned& r1, unsigned& r2, unsigned& r3,
                                      const void* p) {
    unsigned a = (unsigned)__cvta_generic_to_shared(p);
    asm volatile("ldmatrix.sync.aligned.m8n8.x4.shared.b16 {%0,%1,%2,%3}, [%4];"
                 : "=r"(r0), "=r"(r1), "=r"(r2), "=r"(r3) : "r"(a));
}
__device__ __forceinline__ void ldsm4t(unsigned& r0, unsigned& r1, unsigned& r2, unsigned& r3,
                                       const void* p) {
    unsigned a = (unsigned)__cvta_generic_to_shared(p);
    asm volatile("ldmatrix.sync.aligned.m8n8.x4.trans.shared.b16 {%0,%1,%2,%3}, [%4];"
                 : "=r"(r0), "=r"(r1), "=r"(r2), "=r"(r3) : "r"(a));
}
__device__ __forceinline__ void cpa16(void* dst, const void* src) {
    unsigned d = (unsigned)__cvta_generic_to_shared(dst);
    asm volatile("cp.async.ca.shared.global [%0], [%1], 16;" :: "r"(d), "l"(src));
}

// ---------------------------------------------------------------------------
// fp32 -> fp16: x (262144 vec4) + Wq/Wk/Wv/Wo (16384 vec4 each) = 327680
__global__ __launch_bounds__(256) void cvt_kernel(
    const float* __restrict__ x,
    const float* __restrict__ Wq, const float* __restrict__ Wk,
    const float* __restrict__ Wv, const float* __restrict__ Wo)
{
    int idx = blockIdx.x * 256 + threadIdx.x;
    const float4* src;
    uint2* dst;
    int base;
    if (idx < 262144)      { src = (const float4*)x;  dst = (uint2*)g_xh;  base = idx; }
    else if (idx < 278528) { src = (const float4*)Wq; dst = (uint2*)g_wqh; base = idx - 262144; }
    else if (idx < 294912) { src = (const float4*)Wk; dst = (uint2*)g_wkh; base = idx - 278528; }
    else if (idx < 311296) { src = (const float4*)Wv; dst = (uint2*)g_wvh; base = idx - 294912; }
    else                   { src = (const float4*)Wo; dst = (uint2*)g_woh; base = idx - 311296; }
    float4 v = src[base];
    uint2 o = { h2u(pkh2(v.x, v.y)), h2u(pkh2(v.z, v.w)) };
    dst[base] = o;
}

// ---------------------------------------------------------------------------
// fp16 tensor-core QKV GEMM (validated R10 version). grid (NPIX/128, 12).
__global__ __launch_bounds__(256) void gemm_qkv_h(
    const float* __restrict__ bq, const float* __restrict__ bk,
    const float* __restrict__ bv)
{
    __shared__ alignas(16) __half Xs[2][32][136];
    __shared__ alignas(16) __half Ws[2][64][40];

    int sel = blockIdx.y >> 2;
    const __half* Wsrc = (sel == 0) ? g_wqh : (sel == 1) ? g_wkh : g_wvh;
    const float* bias  = (sel == 0) ? bq : (sel == 1) ? bk : bv;
    __half* Y          = (sel == 0) ? g_qh : (sel == 1) ? g_kh : g_vh;
    const float os = (sel == 0) ? (0.17677669529663687f * 1.4426950408889634f) : 1.0f;

    int t = threadIdx.x, lane = t & 31, w = t >> 5;
    int nb = blockIdx.x * 128, ob = (blockIdx.y & 3) * 64;
    int gr = lane >> 2, qt = lane & 3;
    int g  = lane >> 3;

    int xrow = t >> 3, xcol = (t & 7) * 16;
    int wrow = t >> 2, wcol = (t & 3) * 8;
    const __half* xsrc = g_xh + (size_t)xrow * NPIX + nb + xcol;
    const __half* wsrc = Wsrc + (size_t)(ob + wrow) * CH + wcol;

    float acc[8][4] = {};

    cpa16(&Xs[0][xrow][xcol],     xsrc);
    cpa16(&Xs[0][xrow][xcol + 8], xsrc + 8);
    cpa16(&Ws[0][wrow][wcol],     wsrc);
    asm volatile("cp.async.commit_group;");

    for (int c = 0; c < 8; c++) {
        int b = c & 1;
        if (c < 7) {
            const __half* xs = xsrc + (size_t)(c + 1) * 32 * NPIX;
            const __half* ws = wsrc + (c + 1) * 32;
            cpa16(&Xs[b ^ 1][xrow][xcol],     xs);
            cpa16(&Xs[b ^ 1][xrow][xcol + 8], xs + 8);
            cpa16(&Ws[b ^ 1][wrow][wcol],     ws);
            asm volatile("cp.async.commit_group;");
            asm volatile("cp.async.wait_group 1;");
        } else {
            asm volatile("cp.async.wait_group 0;");
        }
        __syncthreads();

        unsigned aa0[4], aa1[4];
        ldsm4t(aa0[0], aa0[2], aa0[1], aa0[3],
               &Xs[b][(g & 1) * 8 + (lane & 7)][16 * w + (g >> 1) * 8]);
        ldsm4t(aa1[0], aa1[2], aa1[1], aa1[3],
               &Xs[b][16 + (g & 1) * 8 + (lane & 7)][16 * w + (g >> 1) * 8]);

        #pragma unroll
        for (int nt = 0; nt < 8; nt++) {
            unsigned b0, b1, b2, b3;
            ldsm4(b0, b1, b2, b3, &Ws[b][nt * 8 + (lane & 7)][(lane >> 3) * 8]);
            mma16h(acc[nt][0], acc[nt][1], acc[nt][2], acc[nt][3],
                   aa0[0], aa0[1], aa0[2], aa0[3], b0, b1);
            mma16h(acc[nt][0], acc[nt][1], acc[nt][2], acc[nt][3],
                   aa1[0], aa1[1], aa1[2], aa1[3], b2, b3);
        }
        __syncthreads();
    }

    int r0 = nb + 16 * w + gr, r1 = r0 + 8;
    #pragma unroll
    for (int nt = 0; nt < 8; nt++) {
        int col = ob + nt * 8 + 2 * qt;
        float2 bv2 = *(const float2*)&bias[col];
        unsigned lo = h2u(pkh2(os * (acc[nt][0] + bv2.x), os * (acc[nt][1] + bv2.y)));
        unsigned hi = h2u(pkh2(os * (acc[nt][2] + bv2.x), os * (acc[nt][3] + bv2.y)));
        *(unsigned*)&Y[(size_t)r0 * CH + col] = lo;
        *(unsigned*)&Y[(size_t)r1 * CH + col] = hi;
    }
}

// ---------------------------------------------------------------------------
// fp16 tensor-core output GEMM with residual (validated R10 version).
__global__ __launch_bounds__(256) void gemm_o_h(
    const float* __restrict__ bias, const float* __restrict__ resid)
{
    __shared__ alignas(16) __half As[2][128][40];
    __shared__ alignas(16) __half Ws[2][64][40];

    int t = threadIdx.x, lane = t & 31, w = t >> 5;
    int nb = blockIdx.x * 128, ob = blockIdx.y * 64;
    int gr = lane >> 2, qt = lane & 3;

    int arow = t >> 1, acol = (t & 1) * 16;
    int wrow = t >> 2, wcol = (t & 3) * 8;
    const __half* asrc = g_atth + (size_t)(nb + arow) * CH + acol;
    const __half* wsrc = g_woh + (size_t)(ob + wrow) * CH + wcol;

    float acc[8][4] = {};

    cpa16(&As[0][arow][acol],     asrc);
    cpa16(&As[0][arow][acol + 8], asrc + 8);
    cpa16(&Ws[0][wrow][wcol],     wsrc);
    asm volatile("cp.async.commit_group;");

    for (int c = 0; c < 8; c++) {
        int b = c & 1;
        if (c < 7) {
            const __half* as = asrc + (c + 1) * 32;
            const __half* ws = wsrc + (c + 1) * 32;
            cpa16(&As[b ^ 1][arow][acol],     as);
            cpa16(&As[b ^ 1][arow][acol + 8], as + 8);
            cpa16(&Ws[b ^ 1][wrow][wcol],     ws);
            asm volatile("cp.async.commit_group;");
            asm volatile("cp.async.wait_group 1;");
        } else {
            asm volatile("cp.async.wait_group 0;");
        }
        __syncthreads();

        unsigned aa0[4], aa1[4];
        ldsm4(aa0[0], aa0[1], aa0[2], aa0[3],
              &As[b][16 * w + (lane & 15)][(lane >> 4) * 8]);
        ldsm4(aa1[0], aa1[1], aa1[2], aa1[3],
              &As[b][16 * w + (lane & 15)][16 + (lane >> 4) * 8]);

        #pragma unroll
        for (int nt = 0; nt < 8; nt++) {
            unsigned b0, b1, b2, b3;
            ldsm4(b0, b1, b2, b3, &Ws[b][nt * 8 + (lane & 7)][(lane >> 3) * 8]);
            mma16h(acc[nt][0], acc[nt][1], acc[nt][2], acc[nt][3],
                   aa0[0], aa0[1], aa0[2], aa0[3], b0, b1);
            mma16h(acc[nt][0], acc[nt][1], acc[nt][2], acc[nt][3],
                   aa1[0], aa1[1], aa1[2], aa1[3], b2, b3);
        }
        __syncthreads();
    }

    int r0 = nb + 16 * w + gr, r1 = r0 + 8;
    #pragma unroll
    for (int nt = 0; nt < 8; nt++) {
        int col = ob + nt * 8 + 2 * qt;
        float2 bv2 = *(const float2*)&bias[col];
        float2 lo = { acc[nt][0] + bv2.x + resid[(size_t)col * NPIX + r0],
                      acc[nt][1] + bv2.y + resid[(size_t)(col + 1) * NPIX + r0] };
        float2 hi = { acc[nt][2] + bv2.x + resid[(size_t)col * NPIX + r1],
                      acc[nt][3] + bv2.y + resid[(size_t)(col + 1) * NPIX + r1] };
        *(float2*)&g_y2[(size_t)r0 * CH + col] = lo;
        *(float2*)&g_y2[(size_t)r1 * CH + col] = hi;
    }
}

// ---------------------------------------------------------------------------
// Flash attention. CTA: 1 head x 128 q-rows, 8 warps.
// half2 softmax; mask applied after exp (z-multiply); 3-stage cp.async
// pipeline with ONE barrier per iteration.
__global__ __launch_bounds__(256, 2) void attn_kernel(const int* __restrict__ mask)
{
    __shared__ alignas(16) __half Ksh[3][64][40];
    __shared__ alignas(16) __half Vsh[3][64][40];

    const unsigned F = 0xffffffffu;
    int t    = threadIdx.x;
    int lane = t & 31;
    int w    = t >> 5;
    int h    = blockIdx.y;
    int qb   = blockIdx.x * 128;
    int gr   = lane >> 2;
    int qt   = lane & 3;
    int hoff = h * HD;

    int r_lo = qb + w * 16 + gr;
    int r_hi = r_lo + 8;

    unsigned qa[2][4];
    {
        const __half* ql  = g_qh + (size_t)r_lo * CH + hoff;
        const __half* qh2 = g_qh + (size_t)r_hi * CH + hoff;
        #pragma unroll
        for (int kc = 0; kc < 2; kc++) {
            qa[kc][0] = *(const unsigned*)(ql  + 16 * kc + 2 * qt);
            qa[kc][1] = *(const unsigned*)(qh2 + 16 * kc + 2 * qt);
            qa[kc][2] = *(const unsigned*)(ql  + 16 * kc + 8 + 2 * qt);
            qa[kc][3] = *(const unsigned*)(qh2 + 16 * kc + 8 + 2 * qt);
        }
    }

    // K/V staging: threads 0-127 -> K, 128-255 -> V; 2x 16B cp.async each
    int su   = t & 127;
    int skey = su >> 1, shh = su & 1;
    bool isV = (t >= 128);
    const __half* src0 = (isV ? g_vh : g_kh) + (size_t)skey * CH + hoff + shh * 16;

    float oc[4][4] = {};
    float Lc0 = 0.f, Lc1 = 0.f, Lc2 = 0.f, Lc3 = 0.f;
    __half2 M0h = __float2half2_rn(-60000.f);
    __half2 M1h = M0h;

    const unsigned bL = (gr == 0) ? 0x3C003C00u : 0u;

    const size_t mrow_lo = ((size_t)h * NPIX + r_lo) * NPIX;
    const size_t mrow_hi = ((size_t)h * NPIX + r_hi) * NPIX;

    // prologue: stage blocks 0 and 1
    #pragma unroll
    for (int pb = 0; pb < 2; pb++) {
        const __half* sp = src0 + (size_t)pb * 64 * CH;
        __half* d = isV ? &Vsh[pb][skey][shh * 16] : &Ksh[pb][skey][shh * 16];
        cpa16(d,     sp);
        cpa16(d + 8, sp + 8);
        asm volatile("cp.async.commit_group;");
    }

    for (int kb = 0; kb < 64; kb++) {
        int s = kb % 3;

        // mask loads for this block (issued before the wait; 0/1 ints)
        int2 mw0[8], mw1[8];
        #pragma unroll
        for (int nt = 0; nt < 8; nt++) {
            size_t c = (size_t)(kb * 64 + nt * 8 + 2 * qt);
            mw0[nt] = *(const int2*)(mask + mrow_lo + c);
            mw1[nt] = *(const int2*)(mask + mrow_hi + c);
        }

        if (kb < 63) asm volatile("cp.async.wait_group 1;");
        else         asm volatile("cp.async.wait_group 0;");
        __syncthreads();           // the ONLY barrier this iteration

        if (kb + 2 < 64) {         // stage kb+2 (slot last read at iter kb-1)
            int sn = (kb + 2) % 3;
            const __half* sp = src0 + (size_t)(kb + 2) * 64 * CH;
            __half* d = isV ? &Vsh[sn][skey][shh * 16] : &Ksh[sn][skey][shh * 16];
            cpa16(d,     sp);
            cpa16(d + 8, sp + 8);
            asm volatile("cp.async.commit_group;");
        }

        // S = Q K^T -> half2 pairs (C-frag cols 2qt,2qt+1 pack naturally)
        __half2 s2lo[8], s2hi[8];
        #pragma unroll
        for (int nt = 0; nt < 8; nt++) {
            unsigned r0, r1, r2, r3;
            ldsm4(r0, r1, r2, r3, &Ksh[s][nt * 8 + (lane & 7)][(lane >> 3) * 8]);
            float c0 = 0.f, c1 = 0.f, c2 = 0.f, c3 = 0.f;
            mma16h(c0, c1, c2, c3, qa[0][0], qa[0][1], qa[0][2], qa[0][3], r0, r1);
            mma16h(c0, c1, c2, c3, qa[1][0], qa[1][1], qa[1][2], qa[1][3], r2, r3);
            s2lo[nt] = pkh2(c0, c1);
            s2hi[nt] = pkh2(c2, c3);
        }

        // row max over ALL scores (masked included -- offset cancels in ratio)
        __half2 m2lo = s2lo[0], m2hi = s2hi[0];
        #pragma unroll
        for (int nt = 1; nt < 8; nt++) {
            m2lo = __hmax2(m2lo, s2lo[nt]);
            m2hi = __hmax2(m2hi, s2hi[nt]);
        }
        m2lo = __hmax2(m2lo, __lowhigh2highlow(m2lo));
        m2hi = __hmax2(m2hi, __lowhigh2highlow(m2hi));
        m2lo = hmax2shfl(m2lo, 1);  m2lo = hmax2shfl(m2lo, 2);
        m2hi = hmax2shfl(m2hi, 1);  m2hi = hmax2shfl(m2hi, 2);

        __half2 Mn0 = __hmax2(M0h, m2lo);
        __half2 Mn1 = __hmax2(M1h, m2hi);
        float a0 = fexp2(__low2float(M0h) - __low2float(Mn0));
        float a1 = fexp2(__low2float(M1h) - __low2float(Mn1));
        M0h = Mn0; M1h = Mn1;

        #pragma unroll
        for (int dt = 0; dt < 4; dt++) {
            oc[dt][0] *= a0; oc[dt][1] *= a0;
            oc[dt][2] *= a1; oc[dt][3] *= a1;
        }
        Lc0 *= a0; Lc2 *= a1;

        // P = exp2(S - M) * zmask ; O += P V ; L += P 1
        int vrow0 = ((lane >> 3) & 1) * 8 + (lane & 7);
        int vcol0 = ((lane >> 3) >> 1) * 8;
        #pragma unroll
        for (int j = 0; j < 4; j++) {
            unsigned z0 = (unsigned)mw0[2*j].x   * 0x3C00u + (unsigned)mw0[2*j].y   * 0x3C000000u;
            unsigned z1 = (unsigned)mw1[2*j].x   * 0x3C00u + (unsigned)mw1[2*j].y   * 0x3C000000u;
            unsigned z2 = (unsigned)mw0[2*j+1].x * 0x3C00u + (unsigned)mw0[2*j+1].y * 0x3C000000u;
            unsigned z3 = (unsigned)mw1[2*j+1].x * 0x3C00u + (unsigned)mw1[2*j+1].y * 0x3C000000u;
            __half2 pa0 = h2exp2z(__hsub2(s2lo[2*j],   M0h), z0);
            __half2 pa1 = h2exp2z(__hsub2(s2hi[2*j],   M1h), z1);
            __half2 pa2 = h2exp2z(__hsub2(s2lo[2*j+1], M0h), z2);
            __half2 pa3 = h2exp2z(__hsub2(s2hi[2*j+1], M1h), z3);
            unsigned a0u = h2u(pa0), a1u = h2u(pa1), a2u = h2u(pa2), a3u = h2u(pa3);
            unsigned b0, b1, b2, b3;
            ldsm4t(b0, b1, b2, b3, &Vsh[s][16 * j + vrow0][vcol0]);
            mma16h(oc[0][0], oc[0][1], oc[0][2], oc[0][3], a0u, a1u, a2u, a3u, b0, b1);
            mma16h(oc[1][0], oc[1][1], oc[1][2], oc[1][3], a0u, a1u, a2u, a3u, b2, b3);
            ldsm4t(b0, b1, b2, b3, &Vsh[s][16 * j + vrow0][16 + vcol0]);
            mma16h(oc[2][0], oc[2][1], oc[2][2], oc[2][3], a0u, a1u, a2u, a3u, b0, b1);
            mma16h(oc[3][0], oc[3][1], oc[3][2], oc[3][3], a0u, a1u, a2u, a3u, b2, b3);
            mma16h(Lc0, Lc1, Lc2, Lc3, a0u, a1u, a2u, a3u, bL, bL);
        }
        // no end-of-loop barrier (3-stage pipeline makes it redundant)
    }

    float L_lo = __shfl_sync(F, Lc0, lane & ~3);
    float L_hi = __shfl_sync(F, Lc2, lane & ~3);

    float rl0 = 1.0f / L_lo;
    float rl1 = 1.0f / L_hi;
    #pragma unroll
    for (int dt = 0; dt < 4; dt++) {
        int cb = hoff + dt * 8 + 2 * qt;
        unsigned lo = h2u(pkh2(oc[dt][0] * rl0, oc[dt][1] * rl0));
        unsigned hi = h2u(pkh2(oc[dt][2] * rl1, oc[dt][3] * rl1));
        *(unsigned*)&g_atth[(size_t)r_lo * CH + cb] = lo;
        *(unsigned*)&g_atth[(size_t)r_hi * CH + cb] = hi;
    }
}

// ---------------------------------------------------------------------------
__global__ __launch_bounds__(256) void ln_kernel(
    const float* __restrict__ gamma, const float* __restrict__ beta,
    float* __restrict__ out)
{
    __shared__ float tile[32][257];
    __shared__ float mu_s[32], rs_s[32];
    const unsigned FULL = 0xffffffffu;

    int t    = threadIdx.x;
    int pb   = blockIdx.x * 32;
    int lane = t & 31;
    int w    = t >> 5;

    #pragma unroll
    for (int i = 0; i < 32; i++)
        tile[i][t] = g_y2[(size_t)(pb + i) * CH + t];
    __syncthreads();

    #pragma unroll
    for (int pi = 0; pi < 4; pi++) {
        int p = w + 8 * pi;
        float sm = 0.f, sq = 0.f;
        #pragma unroll
        for (int c = 0; c < CH; c += 32) {
            float xv = tile[p][c + lane];
            sm += xv;
            sq  = fmaf(xv, xv, sq);
        }
        #pragma unroll
        for (int off = 16; off > 0; off >>= 1) {
            sm += __shfl_xor_sync(FULL, sm, off);
            sq += __shfl_xor_sync(FULL, sq, off);
        }
        if (lane == 0) {
            float mu  = sm * (1.0f / CH);
            float var = sq * (1.0f / CH) - mu * mu;
            mu_s[p] = mu;
            rs_s[p] = rsqrtf(var + 1e-5f);
        }
    }
    __syncthreads();

    float mu = mu_s[lane];
    float rs = rs_s[lane];
    #pragma unroll
    for (int i = 0; i < 32; i++) {
        int c = w + 8 * i;
        float g = gamma[c], b = beta[c];
        out[(size_t)c * NPIX + pb + lane] = (tile[lane][c] - mu) * rs * g + b;
    }
}

// ---------------------------------------------------------------------------
extern "C" void kernel_launch(void* const* d_in, const int* in_sizes, int n_in,
                              void* d_out, int out_size)
{
    const float* x    = (const float*)d_in[0];
    const int*   mask = (const int*)d_in[1];
    const float* Wq = (const float*)d_in[2];
    const float* bq = (const float*)d_in[3];
    const float* Wk = (const float*)d_in[4];
    const float* bk = (const float*)d_in[5];
    const float* Wv = (const float*)d_in[6];
    const float* bv = (const float*)d_in[7];
    const float* Wo = (const float*)d_in[8];
    const float* bo = (const float*)d_in[9];
    const float* gamma = (const float*)d_in[10];
    const float* beta  = (const float*)d_in[11];
    float* out = (float*)d_out;

    cvt_kernel<<<1280, 256>>>(x, Wq, Wk, Wv, Wo);
    gemm_qkv_h<<<dim3(NPIX / 128, 12), 256>>>(bq, bk, bv);
    attn_kernel<<<dim3(NPIX / 128, NH), 256>>>(mask);
    gemm_o_h<<<dim3(NPIX / 128, CH / 64), 256>>>(bo, x);
    ln_kernel<<<NPIX / 32, 256>>>(gamma, beta, out);
}

// round 16
// speedup vs baseline: 1.5727x; 1.0090x over previous
#include <cuda_runtime.h>
#include <cuda_fp16.h>
#include <math.h>
#include <stdint.h>

// EnhancedSparseAttention: B=1, C=256, H=W=64 (N=4096), 8 heads, hd=32
//  0) cvt: x, Wq/Wk/Wv/Wo -> fp16
//  1) q/k/v = W @ x + b       fp16 tensor-core GEMM -> fp16 [n][c] (q scaled)
//  2) flash attention: QK^T mma with fp16 accum (S lands packed), mask after
//     exp via zero-multiply, ballot-guarded alpha rescale, 3-stage cp.async
//  3) y2 = x + Wo @ att + bo  fp16 tensor-core GEMM, fp32 accum/output
//  4) LayerNorm over channels, write [c][n]
// mask arrives as int32 0/1 (bool -> int32 harness conversion).

constexpr int CH   = 256;
constexpr int NPIX = 4096;
constexpr int NH   = 8;
constexpr int HD   = 32;

__device__ __half g_qh  [NPIX * CH];
__device__ __half g_kh  [NPIX * CH];
__device__ __half g_vh  [NPIX * CH];
__device__ __half g_xh  [CH * NPIX];
__device__ __half g_wqh [CH * CH];
__device__ __half g_wkh [CH * CH];
__device__ __half g_wvh [CH * CH];
__device__ __half g_woh [CH * CH];
__device__ __half g_atth[NPIX * CH];
__device__ float  g_y2  [NPIX * CH];

// ---------------------------------------------------------------------------
// fp32 exp2 (x <= 0), used only for the per-block alpha rescales.
__device__ __forceinline__ float fexp2(float x) {
    x = fmaxf(x, -126.0f);
    float r = x + 12582912.0f;            // 1.5*2^23: RN -> integer in low bits
    int   i = __float_as_int(r);
    float f = x - (r - 12582912.0f);      // f in [-0.5, 0.5]
    float p = fmaf(f, 1.3333558e-3f, 9.6181291e-3f);
    p = fmaf(f, p, 5.5504109e-2f);
    p = fmaf(f, p, 2.4022651e-1f);
    p = fmaf(f, p, 6.9314718e-1f);
    p = fmaf(f, p, 1.0f);
    return p * __int_as_float((i + (int)(127 - 0x4B400000)) << 23);
}

// half2 exp2 for x <= 0 with external zero-mask z (half2 {1,0} bit pattern).
// Clamp at -14 (genuine scores never reach it; masked entries killed by z).
__device__ __forceinline__ __half2 h2exp2z(__half2 x, unsigned zu) {
    __half2 xc = __hmax2(x, __float2half2_rn(-14.0f));
    __half2 mg = __float2half2_rn(1536.0f);           // 1.5*2^10
    __half2 r  = __hadd2(xc, mg);                     // RN -> int in mantissa
    __half2 f  = __hsub2(xc, __hsub2(r, mg));         // f in [-0.5, 0.5]
    __half2 p  = __hfma2(f, __float2half2_rn(9.6181291e-3f), __float2half2_rn(5.5504109e-2f));
    p = __hfma2(f, p, __float2half2_rn(2.4022651e-1f));
    p = __hfma2(f, p, __float2half2_rn(6.9314718e-1f));
    p = __hfma2(f, p, __float2half2_rn(1.0f));
    unsigned ru = *reinterpret_cast<unsigned*>(&r);
    unsigned eu = ((ru & 0x03FF03FFu) - 0x01F101F1u) << 10;   // 2^n per lane
    __half2 e = *reinterpret_cast<__half2*>(&eu);
    __half2 z = *reinterpret_cast<__half2*>(&zu);
    return __hmul2(__hmul2(p, e), z);
}

// pack two f32 -> f16x2 (lo in low half)
__device__ __forceinline__ __half2 pkh2(float lo, float hi) {
    unsigned r;
    asm("cvt.rn.f16x2.f32 %0, %1, %2;" : "=r"(r) : "f"(hi), "f"(lo));
    return *reinterpret_cast<__half2*>(&r);
}
__device__ __forceinline__ unsigned h2u(__half2 h) {
    return *reinterpret_cast<unsigned*>(&h);
}
__device__ __forceinline__ __half2 u2h(unsigned u) {
    return *reinterpret_cast<__half2*>(&u);
}
__device__ __forceinline__ __half2 hmax2shfl(__half2 v, int m) {
    unsigned o = __shfl_xor_sync(0xffffffffu, h2u(v), m);
    return __hmax2(v, u2h(o));
}

__device__ __forceinline__ void mma16h(float& c0, float& c1, float& c2, float& c3,
                                       unsigned a0, unsigned a1, unsigned a2, unsigned a3,
                                       unsigned b0, unsigned b1) {
    asm("mma.sync.aligned.m16n8k16.row.col.f32.f16.f16.f32 "
        "{%0,%1,%2,%3}, {%4,%5,%6,%7}, {%8,%9}, {%0,%1,%2,%3};"
        : "+f"(c0), "+f"(c1), "+f"(c2), "+f"(c3)
        : "r"(a0), "r"(a1), "r"(a2), "r"(a3), "r"(b0), "r"(b1));
}

// fp16-accumulate variant: D fragment {d0,d1} holds {row gr cols 2qt,2qt+1}
// and {row gr+8 cols 2qt,2qt+1} as packed half2 -- exactly s2lo/s2hi.
__device__ __forceinline__ void mma16hh(unsigned& d0, unsigned& d1,
                                        unsigned a0, unsigned a1, unsigned a2, unsigned a3,
                                        unsigned b0, unsigned b1) {
    asm("mma.sync.aligned.m16n8k16.row.col.f16.f16.f16.f16 "
        "{%0,%1}, {%2,%3,%4,%5}, {%6,%7}, {%0,%1};"
        : "+r"(d0), "+r"(d1)
        : "r"(a0), "r"(a1), "r"(a2), "r"(a3), "r"(b0), "r"(b1));
}

__device__ __forceinline__ void ldsm4(unsigned& r0, unsigned& r1, unsigned& r2, unsigned& r3,
                                      const void* p) {
    unsigned a = (unsigned)__cvta_generic_to_shared(p);
    asm volatile("ldmatrix.sync.aligned.m8n8.x4.shared.b16 {%0,%1,%2,%3}, [%4];"
                 : "=r"(r0), "=r"(r1), "=r"(r2), "=r"(r3) : "r"(a));
}
__device__ __forceinline__ void ldsm4t(unsigned& r0, unsigned& r1, unsigned& r2, unsigned& r3,
                                       const void* p) {
    unsigned a = (unsigned)__cvta_generic_to_shared(p);
    asm volatile("ldmatrix.sync.aligned.m8n8.x4.trans.shared.b16 {%0,%1,%2,%3}, [%4];"
                 : "=r"(r0), "=r"(r1), "=r"(r2), "=r"(r3) : "r"(a));
}
__device__ __forceinline__ void cpa16(void* dst, const void* src) {
    unsigned d = (unsigned)__cvta_generic_to_shared(dst);
    asm volatile("cp.async.ca.shared.global [%0], [%1], 16;" :: "r"(d), "l"(src));
}

// ---------------------------------------------------------------------------
// fp32 -> fp16: x (262144 vec4) + Wq/Wk/Wv/Wo (16384 vec4 each) = 327680
__global__ __launch_bounds__(256) void cvt_kernel(
    const float* __restrict__ x,
    const float* __restrict__ Wq, const float* __restrict__ Wk,
    const float* __restrict__ Wv, const float* __restrict__ Wo)
{
    int idx = blockIdx.x * 256 + threadIdx.x;
    const float4* src;
    uint2* dst;
    int base;
    if (idx < 262144)      { src = (const float4*)x;  dst = (uint2*)g_xh;  base = idx; }
    else if (idx < 278528) { src = (const float4*)Wq; dst = (uint2*)g_wqh; base = idx - 262144; }
    else if (idx < 294912) { src = (const float4*)Wk; dst = (uint2*)g_wkh; base = idx - 278528; }
    else if (idx < 311296) { src = (const float4*)Wv; dst = (uint2*)g_wvh; base = idx - 294912; }
    else                   { src = (const float4*)Wo; dst = (uint2*)g_woh; base = idx - 311296; }
    float4 v = src[base];
    uint2 o = { h2u(pkh2(v.x, v.y)), h2u(pkh2(v.z, v.w)) };
    dst[base] = o;
}

// ---------------------------------------------------------------------------
// fp16 tensor-core QKV GEMM (validated R10 version). grid (NPIX/128, 12).
__global__ __launch_bounds__(256) void gemm_qkv_h(
    const float* __restrict__ bq, const float* __restrict__ bk,
    const float* __restrict__ bv)
{
    __shared__ alignas(16) __half Xs[2][32][136];
    __shared__ alignas(16) __half Ws[2][64][40];

    int sel = blockIdx.y >> 2;
    const __half* Wsrc = (sel == 0) ? g_wqh : (sel == 1) ? g_wkh : g_wvh;
    const float* bias  = (sel == 0) ? bq : (sel == 1) ? bk : bv;
    __half* Y          = (sel == 0) ? g_qh : (sel == 1) ? g_kh : g_vh;
    const float os = (sel == 0) ? (0.17677669529663687f * 1.4426950408889634f) : 1.0f;

    int t = threadIdx.x, lane = t & 31, w = t >> 5;
    int nb = blockIdx.x * 128, ob = (blockIdx.y & 3) * 64;
    int gr = lane >> 2, qt = lane & 3;
    int g  = lane >> 3;

    int xrow = t >> 3, xcol = (t & 7) * 16;
    int wrow = t >> 2, wcol = (t & 3) * 8;
    const __half* xsrc = g_xh + (size_t)xrow * NPIX + nb + xcol;
    const __half* wsrc = Wsrc + (size_t)(ob + wrow) * CH + wcol;

    float acc[8][4] = {};

    cpa16(&Xs[0][xrow][xcol],     xsrc);
    cpa16(&Xs[0][xrow][xcol + 8], xsrc + 8);
    cpa16(&Ws[0][wrow][wcol],     wsrc);
    asm volatile("cp.async.commit_group;");

    for (int c = 0; c < 8; c++) {
        int b = c & 1;
        if (c < 7) {
            const __half* xs = xsrc + (size_t)(c + 1) * 32 * NPIX;
            const __half* ws = wsrc + (c + 1) * 32;
            cpa16(&Xs[b ^ 1][xrow][xcol],     xs);
            cpa16(&Xs[b ^ 1][xrow][xcol + 8], xs + 8);
            cpa16(&Ws[b ^ 1][wrow][wcol],     ws);
            asm volatile("cp.async.commit_group;");
            asm volatile("cp.async.wait_group 1;");
        } else {
            asm volatile("cp.async.wait_group 0;");
        }
        __syncthreads();

        unsigned aa0[4], aa1[4];
        ldsm4t(aa0[0], aa0[2], aa0[1], aa0[3],
               &Xs[b][(g & 1) * 8 + (lane & 7)][16 * w + (g >> 1) * 8]);
        ldsm4t(aa1[0], aa1[2], aa1[1], aa1[3],
               &Xs[b][16 + (g & 1) * 8 + (lane & 7)][16 * w + (g >> 1) * 8]);

        #pragma unroll
        for (int nt = 0; nt < 8; nt++) {
            unsigned b0, b1, b2, b3;
            ldsm4(b0, b1, b2, b3, &Ws[b][nt * 8 + (lane & 7)][(lane >> 3) * 8]);
            mma16h(acc[nt][0], acc[nt][1], acc[nt][2], acc[nt][3],
                   aa0[0], aa0[1], aa0[2], aa0[3], b0, b1);
            mma16h(acc[nt][0], acc[nt][1], acc[nt][2], acc[nt][3],
                   aa1[0], aa1[1], aa1[2], aa1[3], b2, b3);
        }
        __syncthreads();
    }

    int r0 = nb + 16 * w + gr, r1 = r0 + 8;
    #pragma unroll
    for (int nt = 0; nt < 8; nt++) {
        int col = ob + nt * 8 + 2 * qt;
        float2 bv2 = *(const float2*)&bias[col];
        unsigned lo = h2u(pkh2(os * (acc[nt][0] + bv2.x), os * (acc[nt][1] + bv2.y)));
        unsigned hi = h2u(pkh2(os * (acc[nt][2] + bv2.x), os * (acc[nt][3] + bv2.y)));
        *(unsigned*)&Y[(size_t)r0 * CH + col] = lo;
        *(unsigned*)&Y[(size_t)r1 * CH + col] = hi;
    }
}

// ---------------------------------------------------------------------------
// fp16 tensor-core output GEMM with residual (validated R10 version).
__global__ __launch_bounds__(256) void gemm_o_h(
    const float* __restrict__ bias, const float* __restrict__ resid)
{
    __shared__ alignas(16) __half As[2][128][40];
    __shared__ alignas(16) __half Ws[2][64][40];

    int t = threadIdx.x, lane = t & 31, w = t >> 5;
    int nb = blockIdx.x * 128, ob = blockIdx.y * 64;
    int gr = lane >> 2, qt = lane & 3;

    int arow = t >> 1, acol = (t & 1) * 16;
    int wrow = t >> 2, wcol = (t & 3) * 8;
    const __half* asrc = g_atth + (size_t)(nb + arow) * CH + acol;
    const __half* wsrc = g_woh + (size_t)(ob + wrow) * CH + wcol;

    float acc[8][4] = {};

    cpa16(&As[0][arow][acol],     asrc);
    cpa16(&As[0][arow][acol + 8], asrc + 8);
    cpa16(&Ws[0][wrow][wcol],     wsrc);
    asm volatile("cp.async.commit_group;");

    for (int c = 0; c < 8; c++) {
        int b = c & 1;
        if (c < 7) {
            const __half* as = asrc + (c + 1) * 32;
            const __half* ws = wsrc + (c + 1) * 32;
            cpa16(&As[b ^ 1][arow][acol],     as);
            cpa16(&As[b ^ 1][arow][acol + 8], as + 8);
            cpa16(&Ws[b ^ 1][wrow][wcol],     ws);
            asm volatile("cp.async.commit_group;");
            asm volatile("cp.async.wait_group 1;");
        } else {
            asm volatile("cp.async.wait_group 0;");
        }
        __syncthreads();

        unsigned aa0[4], aa1[4];
        ldsm4(aa0[0], aa0[1], aa0[2], aa0[3],
              &As[b][16 * w + (lane & 15)][(lane >> 4) * 8]);
        ldsm4(aa1[0], aa1[1], aa1[2], aa1[3],
              &As[b][16 * w + (lane & 15)][16 + (lane >> 4) * 8]);

        #pragma unroll
        for (int nt = 0; nt < 8; nt++) {
            unsigned b0, b1, b2, b3;
            ldsm4(b0, b1, b2, b3, &Ws[b][nt * 8 + (lane & 7)][(lane >> 3) * 8]);
            mma16h(acc[nt][0], acc[nt][1], acc[nt][2], acc[nt][3],
                   aa0[0], aa0[1], aa0[2], aa0[3], b0, b1);
            mma16h(acc[nt][0], acc[nt][1], acc[nt][2], acc[nt][3],
                   aa1[0], aa1[1], aa1[2], aa1[3], b2, b3);
        }
        __syncthreads();
    }

    int r0 = nb + 16 * w + gr, r1 = r0 + 8;
    #pragma unroll
    for (int nt = 0; nt < 8; nt++) {
        int col = ob + nt * 8 + 2 * qt;
        float2 bv2 = *(const float2*)&bias[col];
        float2 lo = { acc[nt][0] + bv2.x + resid[(size_t)col * NPIX + r0],
                      acc[nt][1] + bv2.y + resid[(size_t)(col + 1) * NPIX + r0] };
        float2 hi = { acc[nt][2] + bv2.x + resid[(size_t)col * NPIX + r1],
                      acc[nt][3] + bv2.y + resid[(size_t)(col + 1) * NPIX + r1] };
        *(float2*)&g_y2[(size_t)r0 * CH + col] = lo;
        *(float2*)&g_y2[(size_t)r1 * CH + col] = hi;
    }
}

// ---------------------------------------------------------------------------
// Flash attention. CTA: 1 head x 128 q-rows, 8 warps.
// QK^T in fp16-accum mma (S packed for free); mask after exp (z-multiply);
// ballot-guarded alpha rescale; 3-stage cp.async, one barrier per iteration.
__global__ __launch_bounds__(256, 2) void attn_kernel(const int* __restrict__ mask)
{
    __shared__ alignas(16) __half Ksh[3][64][40];
    __shared__ alignas(16) __half Vsh[3][64][40];

    const unsigned F = 0xffffffffu;
    int t    = threadIdx.x;
    int lane = t & 31;
    int w    = t >> 5;
    int h    = blockIdx.y;
    int qb   = blockIdx.x * 128;
    int gr   = lane >> 2;
    int qt   = lane & 3;
    int hoff = h * HD;

    int r_lo = qb + w * 16 + gr;
    int r_hi = r_lo + 8;

    unsigned qa[2][4];
    {
        const __half* ql  = g_qh + (size_t)r_lo * CH + hoff;
        const __half* qh2 = g_qh + (size_t)r_hi * CH + hoff;
        #pragma unroll
        for (int kc = 0; kc < 2; kc++) {
            qa[kc][0] = *(const unsigned*)(ql  + 16 * kc + 2 * qt);
            qa[kc][1] = *(const unsigned*)(qh2 + 16 * kc + 2 * qt);
            qa[kc][2] = *(const unsigned*)(ql  + 16 * kc + 8 + 2 * qt);
            qa[kc][3] = *(const unsigned*)(qh2 + 16 * kc + 8 + 2 * qt);
        }
    }

    // K/V staging: threads 0-127 -> K, 128-255 -> V; 2x 16B cp.async each
    int su   = t & 127;
    int skey = su >> 1, shh = su & 1;
    bool isV = (t >= 128);
    const __half* src0 = (isV ? g_vh : g_kh) + (size_t)skey * CH + hoff + shh * 16;

    float oc[4][4] = {};
    float Lc0 = 0.f, Lc1 = 0.f, Lc2 = 0.f, Lc3 = 0.f;
    __half2 M0h = __float2half2_rn(-60000.f);
    __half2 M1h = M0h;

    const unsigned bL = (gr == 0) ? 0x3C003C00u : 0u;

    const size_t mrow_lo = ((size_t)h * NPIX + r_lo) * NPIX;
    const size_t mrow_hi = ((size_t)h * NPIX + r_hi) * NPIX;

    // prologue: stage blocks 0 and 1
    #pragma unroll
    for (int pb = 0; pb < 2; pb++) {
        const __half* sp = src0 + (size_t)pb * 64 * CH;
        __half* d = isV ? &Vsh[pb][skey][shh * 16] : &Ksh[pb][skey][shh * 16];
        cpa16(d,     sp);
        cpa16(d + 8, sp + 8);
        asm volatile("cp.async.commit_group;");
    }

    for (int kb = 0; kb < 64; kb++) {
        int s = kb % 3;

        // mask loads for this block (issued before the wait; 0/1 ints)
        int2 mw0[8], mw1[8];
        #pragma unroll
        for (int nt = 0; nt < 8; nt++) {
            size_t c = (size_t)(kb * 64 + nt * 8 + 2 * qt);
            mw0[nt] = *(const int2*)(mask + mrow_lo + c);
            mw1[nt] = *(const int2*)(mask + mrow_hi + c);
        }

        if (kb < 63) asm volatile("cp.async.wait_group 1;");
        else         asm volatile("cp.async.wait_group 0;");
        __syncthreads();           // the ONLY barrier this iteration

        if (kb + 2 < 64) {         // stage kb+2 (slot last read at iter kb-1)
            int sn = (kb + 2) % 3;
            const __half* sp = src0 + (size_t)(kb + 2) * 64 * CH;
            __half* d = isV ? &Vsh[sn][skey][shh * 16] : &Ksh[sn][skey][shh * 16];
            cpa16(d,     sp);
            cpa16(d + 8, sp + 8);
            asm volatile("cp.async.commit_group;");
        }

        // S = Q K^T with fp16 accumulators: D-frags ARE the packed score pairs
        __half2 s2lo[8], s2hi[8];
        #pragma unroll
        for (int nt = 0; nt < 8; nt++) {
            unsigned r0, r1, r2, r3;
            ldsm4(r0, r1, r2, r3, &Ksh[s][nt * 8 + (lane & 7)][(lane >> 3) * 8]);
            unsigned d0 = 0, d1 = 0;
            mma16hh(d0, d1, qa[0][0], qa[0][1], qa[0][2], qa[0][3], r0, r1);
            mma16hh(d0, d1, qa[1][0], qa[1][1], qa[1][2], qa[1][3], r2, r3);
            s2lo[nt] = u2h(d0);
            s2hi[nt] = u2h(d1);
        }

        // row max over ALL scores (masked included -- offset cancels in ratio)
        __half2 m2lo = s2lo[0], m2hi = s2hi[0];
        #pragma unroll
        for (int nt = 1; nt < 8; nt++) {
            m2lo = __hmax2(m2lo, s2lo[nt]);
            m2hi = __hmax2(m2hi, s2hi[nt]);
        }
        m2lo = __hmax2(m2lo, __lowhigh2highlow(m2lo));
        m2hi = __hmax2(m2hi, __lowhigh2highlow(m2hi));
        m2lo = hmax2shfl(m2lo, 1);  m2lo = hmax2shfl(m2lo, 2);
        m2hi = hmax2shfl(m2hi, 1);  m2hi = hmax2shfl(m2hi, 2);

        __half2 Mo0 = M0h, Mo1 = M1h;
        __half2 Mn0 = __hmax2(Mo0, m2lo);
        __half2 Mn1 = __hmax2(Mo1, m2hi);
        M0h = Mn0; M1h = Mn1;

        // rescale only if some row in this warp raised its max (alpha != 1)
        bool upd = (h2u(Mn0) != h2u(Mo0)) || (h2u(Mn1) != h2u(Mo1));
        if (__ballot_sync(F, upd)) {
            float a0 = fexp2(__low2float(Mo0) - __low2float(Mn0));
            float a1 = fexp2(__low2float(Mo1) - __low2float(Mn1));
            #pragma unroll
            for (int dt = 0; dt < 4; dt++) {
                oc[dt][0] *= a0; oc[dt][1] *= a0;
                oc[dt][2] *= a1; oc[dt][3] *= a1;
            }
            Lc0 *= a0; Lc2 *= a1;
        }

        // P = exp2(S - M) * zmask ; O += P V ; L += P 1
        int vrow0 = ((lane >> 3) & 1) * 8 + (lane & 7);
        int vcol0 = ((lane >> 3) >> 1) * 8;
        #pragma unroll
        for (int j = 0; j < 4; j++) {
            unsigned z0 = (unsigned)mw0[2*j].x   * 0x3C00u + (unsigned)mw0[2*j].y   * 0x3C000000u;
            unsigned z1 = (unsigned)mw1[2*j].x   * 0x3C00u + (unsigned)mw1[2*j].y   * 0x3C000000u;
            unsigned z2 = (unsigned)mw0[2*j+1].x * 0x3C00u + (unsigned)mw0[2*j+1].y * 0x3C000000u;
            unsigned z3 = (unsigned)mw1[2*j+1].x * 0x3C00u + (unsigned)mw1[2*j+1].y * 0x3C000000u;
            __half2 pa0 = h2exp2z(__hsub2(s2lo[2*j],   M0h), z0);
            __half2 pa1 = h2exp2z(__hsub2(s2hi[2*j],   M1h), z1);
            __half2 pa2 = h2exp2z(__hsub2(s2lo[2*j+1], M0h), z2);
            __half2 pa3 = h2exp2z(__hsub2(s2hi[2*j+1], M1h), z3);
            unsigned a0u = h2u(pa0), a1u = h2u(pa1), a2u = h2u(pa2), a3u = h2u(pa3);
            unsigned b0, b1, b2, b3;
            ldsm4t(b0, b1, b2, b3, &Vsh[s][16 * j + vrow0][vcol0]);
            mma16h(oc[0][0], oc[0][1], oc[0][2], oc[0][3], a0u, a1u, a2u, a3u, b0, b1);
            mma16h(oc[1][0], oc[1][1], oc[1][2], oc[1][3], a0u, a1u, a2u, a3u, b2, b3);
            ldsm4t(b0, b1, b2, b3, &Vsh[s][16 * j + vrow0][16 + vcol0]);
            mma16h(oc[2][0], oc[2][1], oc[2][2], oc[2][3], a0u, a1u, a2u, a3u, b0, b1);
            mma16h(oc[3][0], oc[3][1], oc[3][2], oc[3][3], a0u, a1u, a2u, a3u, b2, b3);
            mma16h(Lc0, Lc1, Lc2, Lc3, a0u, a1u, a2u, a3u, bL, bL);
        }
        // no end-of-loop barrier (3-stage pipeline makes it redundant)
    }

    float L_lo = __shfl_sync(F, Lc0, lane & ~3);
    float L_hi = __shfl_sync(F, Lc2, lane & ~3);

    float rl0 = 1.0f / L_lo;
    float rl1 = 1.0f / L_hi;
    #pragma unroll
    for (int dt = 0; dt < 4; dt++) {
        int cb = hoff + dt * 8 + 2 * qt;
        unsigned lo = h2u(pkh2(oc[dt][0] * rl0, oc[dt][1] * rl0));
        unsigned hi = h2u(pkh2(oc[dt][2] * rl1, oc[dt][3] * rl1));
        *(unsigned*)&g_atth[(size_t)r_lo * CH + cb] = lo;
        *(unsigned*)&g_atth[(size_t)r_hi * CH + cb] = hi;
    }
}

// ---------------------------------------------------------------------------
__global__ __launch_bounds__(256) void ln_kernel(
    const float* __restrict__ gamma, const float* __restrict__ beta,
    float* __restrict__ out)
{
    __shared__ float tile[32][257];
    __shared__ float mu_s[32], rs_s[32];
    const unsigned FULL = 0xffffffffu;

    int t    = threadIdx.x;
    int pb   = blockIdx.x * 32;
    int lane = t & 31;
    int w    = t >> 5;

    #pragma unroll
    for (int i = 0; i < 32; i++)
        tile[i][t] = g_y2[(size_t)(pb + i) * CH + t];
    __syncthreads();

    #pragma unroll
    for (int pi = 0; pi < 4; pi++) {
        int p = w + 8 * pi;
        float sm = 0.f, sq = 0.f;
        #pragma unroll
        for (int c = 0; c < CH; c += 32) {
            float xv = tile[p][c + lane];
            sm += xv;
            sq  = fmaf(xv, xv, sq);
        }
        #pragma unroll
        for (int off = 16; off > 0; off >>= 1) {
            sm += __shfl_xor_sync(FULL, sm, off);
            sq += __shfl_xor_sync(FULL, sq, off);
        }
        if (lane == 0) {
            float mu  = sm * (1.0f / CH);
            float var = sq * (1.0f / CH) - mu * mu;
            mu_s[p] = mu;
            rs_s[p] = rsqrtf(var + 1e-5f);
        }
    }
    __syncthreads();

    float mu = mu_s[lane];
    float rs = rs_s[lane];
    #pragma unroll
    for (int i = 0; i < 32; i++) {
        int c = w + 8 * i;
        float g = gamma[c], b = beta[c];
        out[(size_t)c * NPIX + pb + lane] = (tile[lane][c] - mu) * rs * g + b;
    }
}

// ---------------------------------------------------------------------------
extern "C" void kernel_launch(void* const* d_in, const int* in_sizes, int n_in,
                              void* d_out, int out_size)
{
    const float* x    = (const float*)d_in[0];
    const int*   mask = (const int*)d_in[1];
    const float* Wq = (const float*)d_in[2];
    const float* bq = (const float*)d_in[3];
    const float* Wk = (const float*)d_in[4];
    const float* bk = (const float*)d_in[5];
    const float* Wv = (const float*)d_in[6];
    const float* bv = (const float*)d_in[7];
    const float* Wo = (const float*)d_in[8];
    const float* bo = (const float*)d_in[9];
    const float* gamma = (const float*)d_in[10];
    const float* beta  = (const float*)d_in[11];
    float* out = (float*)d_out;

    cvt_kernel<<<1280, 256>>>(x, Wq, Wk, Wv, Wo);
    gemm_qkv_h<<<dim3(NPIX / 128, 12), 256>>>(bq, bk, bv);
    attn_kernel<<<dim3(NPIX / 128, NH), 256>>>(mask);
    gemm_o_h<<<dim3(NPIX / 128, CH / 64), 256>>>(bo, x);
    ln_kernel<<<NPIX / 32, 256>>>(gamma, beta, out);
}